// round 4
// baseline (speedup 1.0000x reference)
#include <cuda_runtime.h>
#include <cuda_fp16.h>

#define N_GENES 20000
#define UNITS   10000
#define DEG     32
#define BATCH   128

// |feature| transposed to [gene][batch] in fp16: 5.12 MB, L2-resident.
// Row = 256B; each (unit, deg) gather reads one full row, coalesced.
__device__ __half g_featT[(size_t)N_GENES * BATCH];

// ---------------------------------------------------------------------------
// K1: tiled transpose + fabs + fp16.  feature [128, 20000] -> featT [N, B]
// ---------------------------------------------------------------------------
__global__ void transpose_abs_kernel(const float* __restrict__ feature) {
    __shared__ float tile[32][33];               // tile[batch][gene]
    const int gx = blockIdx.x * 32;
    const int bx = blockIdx.y * 32;
    const int tx = threadIdx.x, ty = threadIdx.y;

#pragma unroll
    for (int k = 0; k < 32; k += 8)
        tile[ty + k][tx] = fabsf(feature[(size_t)(bx + ty + k) * N_GENES + (gx + tx)]);
    __syncthreads();

    // Store phase: 32 genes x 16 half2 = 512 tasks over 256 threads.
    // smem reads conflict-free: bank = (2p + g_l) % 32 is a permutation.
    const int t = ty * 32 + tx;
#pragma unroll
    for (int iter = 0; iter < 2; iter++) {
        const int tt  = iter * 256 + t;
        const int g_l = tt >> 4;                 // 0..31
        const int p   = tt & 15;                 // batch pair
        const __half2 h = __floats2half2_rn(tile[2 * p][g_l], tile[2 * p + 1][g_l]);
        *(__half2*)&g_featT[(size_t)(gx + g_l) * BATCH + bx + 2 * p] = h;
    }
}

// ---------------------------------------------------------------------------
// K2: gather-sum. One warp per unit; lane d owns byte-offset of ppi[u][d]'s
// row; broadcast via shfl. half2 accumulation, fp32 flush every 8 degs.
// ---------------------------------------------------------------------------
__global__ void __launch_bounds__(256) ppi_gather_kernel(
    const int*   __restrict__ ppi,     // int32 (JAX x64-disabled)
    const float* __restrict__ kern,
    const float* __restrict__ bias,
    float*       __restrict__ out)
{
    __shared__ float tile[8][BATCH + 4];

    const int lane   = threadIdx.x & 31;
    const int warp   = threadIdx.x >> 5;
    const int u_base = blockIdx.x * 8;
    const int u      = u_base + warp;

    // Pre-shifted row byte-offset (row = 128 halves = 256B); lane's 8B slice
    // folded into the base pointer.
    const int myoff = ppi[(size_t)u * DEG + lane] << 8;
    const char* base = (const char*)g_featT + lane * 8;

    float4 acc = make_float4(0.f, 0.f, 0.f, 0.f);
#pragma unroll
    for (int blk = 0; blk < 4; blk++) {
        __half2 h01 = __floats2half2_rn(0.f, 0.f);
        __half2 h23 = h01;
#pragma unroll
        for (int dd = 0; dd < 8; dd++) {
            const int off = __shfl_sync(0xffffffffu, myoff, blk * 8 + dd);
            const uint2 raw = *(const uint2*)(base + off);
            h01 = __hadd2(h01, *(const __half2*)&raw.x);
            h23 = __hadd2(h23, *(const __half2*)&raw.y);
        }
        const float2 f01 = __half22float2(h01);
        const float2 f23 = __half22float2(h23);
        acc.x += f01.x; acc.y += f01.y; acc.z += f23.x; acc.w += f23.y;
    }

    const float kv = kern[u];
    const float bv = bias[u];
    float4 r;
    r.x = tanhf(fmaf(acc.x, kv, bv));
    r.y = tanhf(fmaf(acc.y, kv, bv));
    r.z = tanhf(fmaf(acc.z, kv, bv));
    r.w = tanhf(fmaf(acc.w, kv, bv));
    *(float4*)&tile[warp][lane * 4] = r;

    __syncthreads();

    // Coalesced output: 8-thread groups write contiguous 32B chunks per row.
    for (int t = threadIdx.x; t < BATCH * 8; t += 256) {
        const int u_l = t & 7;
        const int b   = t >> 3;
        out[(size_t)b * UNITS + (u_base + u_l)] = tile[u_l][b];
    }
}

// ---------------------------------------------------------------------------
extern "C" void kernel_launch(void* const* d_in, const int* in_sizes, int n_in,
                              void* d_out, int out_size) {
    const float* feature = (const float*)d_in[0];
    const int*   ppi     = (const int*)d_in[1];
    const float* kern    = (const float*)d_in[2];
    const float* bias    = (const float*)d_in[3];
    float*       out     = (float*)d_out;

    dim3 tgrid(N_GENES / 32, BATCH / 32);   // (625, 4)
    dim3 tblock(32, 8);
    transpose_abs_kernel<<<tgrid, tblock>>>(feature);

    ppi_gather_kernel<<<UNITS / 8, 256>>>(ppi, kern, bias, out);  // 1250 CTAs
}